// round 15
// baseline (speedup 1.0000x reference)
#include <cuda_runtime.h>
#include <cuda_bf16.h>
#include <cuda_fp16.h>

// Problem constants (shapes fixed by the dataset)
#define F 128
#define HEADS 8
#define NMAX 50000
#define EMAX 600000
#define SLOTS (EMAX + NMAX)
#define SCAN_BLK 256
#define SCAN_ITEMS 4
#define SCAN_TILE (SCAN_BLK * SCAN_ITEMS)   // 1024 counts per block
#define SCAN_MAXB 256                        // up to 256K nodes

// Scratch (device globals: the sanctioned no-alloc workaround)
__device__ float   g_Q[NMAX * F];
__device__ __half2 g_Kh[NMAX * (F / 2)];   // K in fp16 (halved aggr traffic)
__device__ __half2 g_Vh[NMAX * (F / 2)];   // V in fp16
__device__ int   g_cnt[NMAX];       // per-dest degree (incl. self loop)
__device__ int   g_ptr[NMAX + 1];   // CSR row pointers
__device__ int   g_cur[NMAX];       // scatter cursors
__device__ int   g_csr[SLOTS];      // column (source) indices, dest-sorted
__device__ int   g_bsum[SCAN_MAXB]; // per-block count sums
__device__ int   g_boff[SCAN_MAXB]; // inclusive scan of block sums
__device__ int   g_ei32;            // 1 if edge_index is int32, 0 if int64
__device__ int   g_id32;            // 1 if id_index   is int32, 0 if int64

__device__ __forceinline__ int loadIdx(const void* p, long long i, int is32) {
    if (is32) return ((const int*)p)[i];
    return (int)((const long long*)p)[i];
}

// ---------------------------------------------------------------------------
// bf16 split: a = hi + lo + eps, eps ~ 2^-18 |a|  (both halves exact bf16)
// ---------------------------------------------------------------------------
__device__ __forceinline__ void splitb(float a, unsigned short& hi, unsigned short& lo) {
    __nv_bfloat16 h = __float2bfloat16(a);
    float r = a - __bfloat162float(h);     // exact in fp32
    __nv_bfloat16 l = __float2bfloat16(r);
    hi = __bfloat16_as_ushort(h);
    lo = __bfloat16_as_ushort(l);
}

__device__ __forceinline__ unsigned packu(unsigned short e0, unsigned short e1) {
    return (unsigned)e0 | ((unsigned)e1 << 16);   // e0 = even k (low half)
}

__device__ __forceinline__ void mma_bf16(float c[4], const unsigned a[4], const unsigned b[2]) {
    asm volatile(
        "mma.sync.aligned.m16n8k16.row.col.f32.bf16.bf16.f32 "
        "{%0,%1,%2,%3}, {%4,%5,%6,%7}, {%8,%9}, {%0,%1,%2,%3};"
        : "+f"(c[0]), "+f"(c[1]), "+f"(c[2]), "+f"(c[3])
        : "r"(a[0]), "r"(a[1]), "r"(a[2]), "r"(a[3]),
          "r"(b[0]), "r"(b[1]));
}

// ---------------------------------------------------------------------------
// Dtype detection (launch 0): int64 values < 2^31 have all-zero odd (high)
// u32 words; int32 random indices essentially never do. OR-only writes into
// zero-initialized globals => idempotent across graph replays.
// ---------------------------------------------------------------------------
__global__ void k_detect(const unsigned* __restrict__ ei, int eiElems,
                         const unsigned* __restrict__ idx, int idElems) {
    int t = blockIdx.x * blockDim.x + threadIdx.x;  // 0..1023
    int wi = 2 * t + 1;
    if (wi < eiElems && ei[wi] != 0u) atomicOr(&g_ei32, 1);
    if (wi < idElems && idx[wi] != 0u) atomicOr(&g_id32, 1);
}

// ---------------------------------------------------------------------------
// Init: cnt = 1 (self loop)
// ---------------------------------------------------------------------------
__global__ void k_init(int N) {
    int i = blockIdx.x * blockDim.x + threadIdx.x;
    if (i < N) g_cnt[i] = 1;
}

// ---------------------------------------------------------------------------
// CSR build step 1: histogram of destinations
// ---------------------------------------------------------------------------
__global__ void k_hist(const void* __restrict__ ei, int E) {
    int e = blockIdx.x * blockDim.x + threadIdx.x;
    if (e >= E) return;
    int row = loadIdx(ei, e, g_ei32);
    atomicAdd(&g_cnt[row], 1);
}

// ---------------------------------------------------------------------------
// bf16x3 GEMM (launch 3 => ncu-profiled): z=0 Q=relu(xWq+bq) fp32,
// z=1 K=relu(xWk+bk) fp16, z=2 V=xWv fp16.
// K-chunked (32), packed bf16 hi/lo pairs in smem (~27 KB), m16n8k16.
// ---------------------------------------------------------------------------
#define AP 20                    // u32 pair stride for A rows (16 data + 4 pad)
#define WP 136                   // u32 col stride for W pair-rows (128 + 8 pad)
#define KCHUNK 32
#define KPAIRS (KCHUNK / 2)      // 16 pair-rows per chunk
#define GEMM_SMEM_BYTES ((64 * AP * 2 + KPAIRS * WP * 2) * 4)

__global__ void __launch_bounds__(256, 2)
k_gemm(const float* __restrict__ x,
       const float* __restrict__ Wq, const float* __restrict__ bq,
       const float* __restrict__ Wk, const float* __restrict__ bk,
       const float* __restrict__ Wv,
       int N) {
    extern __shared__ unsigned smu[];
    unsigned* Ahi = smu;                  // [64][AP]
    unsigned* Alo = Ahi + 64 * AP;
    unsigned* Whi = Alo + 64 * AP;        // [KPAIRS][WP]
    unsigned* Wlo = Whi + KPAIRS * WP;

    int z = blockIdx.z;
    const float* W    = (z == 0) ? Wq : (z == 1) ? Wk : Wv;
    const float* bias = (z == 0) ? bq : (z == 1) ? bk : nullptr;

    int tid = threadIdx.x;
    int rowBase = blockIdx.x * 64;

    int lane = tid & 31, wid = tid >> 5;
    int g = lane >> 2, t4 = lane & 3;
    int wm = (wid & 1) * 32;
    int wn = (wid >> 1) * 32;

    float c[2][4][4];
    #pragma unroll
    for (int mt = 0; mt < 2; mt++)
        #pragma unroll
        for (int nt = 0; nt < 4; nt++)
            #pragma unroll
            for (int j = 0; j < 4; j++) c[mt][nt][j] = 0.0f;

    for (int kb = 0; kb < F / KCHUNK; kb++) {
        if (kb > 0) __syncthreads();      // protect smem reuse across chunks

        // Stage A chunk: 64 rows x 32 k (512 float4 tasks -> 2 packed u32 each)
        #pragma unroll
        for (int i = tid; i < 64 * 8; i += 256) {
            int r = i >> 3, c4 = (i & 7) << 2;       // k offset in chunk
            int gr = rowBase + r;
            float4 v = make_float4(0.f, 0.f, 0.f, 0.f);
            if (gr < N) v = *(const float4*)(x + (size_t)gr * F + kb * KCHUNK + c4);
            unsigned short hx, lx, hy, ly, hz, lz, hw, lw;
            splitb(v.x, hx, lx); splitb(v.y, hy, ly);
            splitb(v.z, hz, lz); splitb(v.w, hw, lw);
            int pc = c4 >> 1;                        // pair column
            Ahi[r * AP + pc]     = packu(hx, hy);
            Ahi[r * AP + pc + 1] = packu(hz, hw);
            Alo[r * AP + pc]     = packu(lx, ly);
            Alo[r * AP + pc + 1] = packu(lz, lw);
        }
        // Stage W chunk: 16 pair-rows x 128 cols (512 tasks, 2 float4 loads each)
        #pragma unroll
        for (int i = tid; i < 16 * 32; i += 256) {
            int pr = i >> 5, c4 = (i & 31) << 2;     // pair-row, col
            int k0 = kb * KCHUNK + 2 * pr;
            float4 w0 = *(const float4*)(W + (size_t)k0 * F + c4);
            float4 w1 = *(const float4*)(W + (size_t)(k0 + 1) * F + c4);
            const float* a0 = &w0.x; const float* a1 = &w1.x;
            #pragma unroll
            for (int m = 0; m < 4; m++) {
                unsigned short h0, l0, h1, l1;
                splitb(a0[m], h0, l0);
                splitb(a1[m], h1, l1);
                Whi[pr * WP + c4 + m] = packu(h0, h1);   // even k low half
                Wlo[pr * WP + c4 + m] = packu(l0, l1);
            }
        }
        __syncthreads();

        #pragma unroll
        for (int ks = 0; ks < KCHUNK / 16; ks++) {
            int bp = ks * 8;                         // base pair index
            unsigned ah[2][4], al[2][4];
            #pragma unroll
            for (int mt = 0; mt < 2; mt++) {
                int r0 = wm + mt * 16 + g;
                ah[mt][0] = Ahi[r0 * AP + bp + t4];
                ah[mt][1] = Ahi[(r0 + 8) * AP + bp + t4];
                ah[mt][2] = Ahi[r0 * AP + bp + t4 + 4];
                ah[mt][3] = Ahi[(r0 + 8) * AP + bp + t4 + 4];
                al[mt][0] = Alo[r0 * AP + bp + t4];
                al[mt][1] = Alo[(r0 + 8) * AP + bp + t4];
                al[mt][2] = Alo[r0 * AP + bp + t4 + 4];
                al[mt][3] = Alo[(r0 + 8) * AP + bp + t4 + 4];
            }
            unsigned bh[4][2], bl[4][2];
            #pragma unroll
            for (int nt = 0; nt < 4; nt++) {
                int cn = wn + nt * 8 + g;
                bh[nt][0] = Whi[(bp + t4) * WP + cn];
                bh[nt][1] = Whi[(bp + t4 + 4) * WP + cn];
                bl[nt][0] = Wlo[(bp + t4) * WP + cn];
                bl[nt][1] = Wlo[(bp + t4 + 4) * WP + cn];
            }
            #pragma unroll
            for (int mt = 0; mt < 2; mt++)
                #pragma unroll
                for (int nt = 0; nt < 4; nt++) {
                    mma_bf16(c[mt][nt], ah[mt], bh[nt]);
                    mma_bf16(c[mt][nt], ah[mt], bl[nt]);
                    mma_bf16(c[mt][nt], al[mt], bh[nt]);
                }
        }
    }

    // Writeout: z=0 -> fp32 Q (float2); z=1/2 -> fp16 K/V (half2)
    __half2* outh = (z == 1) ? g_Kh : g_Vh;
    #pragma unroll
    for (int mt = 0; mt < 2; mt++) {
        int r0 = rowBase + wm + mt * 16 + g;
        #pragma unroll
        for (int nt = 0; nt < 4; nt++) {
            int cn = wn + nt * 8 + 2 * t4;
            float b0 = bias ? bias[cn] : 0.0f;
            float b1 = bias ? bias[cn + 1] : 0.0f;
            #pragma unroll
            for (int half = 0; half < 2; half++) {
                int rr = r0 + half * 8;
                if (rr >= N) continue;
                float v0 = c[mt][nt][half * 2 + 0] + b0;
                float v1 = c[mt][nt][half * 2 + 1] + b1;
                if (z < 2) { v0 = fmaxf(v0, 0.0f); v1 = fmaxf(v1, 0.0f); }
                if (z == 0) {
                    *(float2*)&g_Q[(size_t)rr * F + cn] = make_float2(v0, v1);
                } else {
                    outh[(size_t)rr * (F / 2) + (cn >> 1)] = __floats2half2_rn(v0, v1);
                }
            }
        }
    }
}

// ---------------------------------------------------------------------------
// Two-level scan, pass A: per-block sums of SCAN_TILE counts
// ---------------------------------------------------------------------------
__global__ void __launch_bounds__(SCAN_BLK) k_bsum(int N) {
    __shared__ int s[SCAN_BLK];
    int b = blockIdx.x, t = threadIdx.x;
    int base = b * SCAN_TILE + t * SCAN_ITEMS;
    int sum = 0;
    #pragma unroll
    for (int j = 0; j < SCAN_ITEMS; j++) {
        int i = base + j;
        if (i < N) sum += g_cnt[i];
    }
    s[t] = sum;
    __syncthreads();
    #pragma unroll
    for (int off = SCAN_BLK / 2; off > 0; off >>= 1) {
        if (t < off) s[t] += s[t + off];
        __syncthreads();
    }
    if (t == 0) g_bsum[b] = s[0];
}

// ---------------------------------------------------------------------------
// Pass B: single small block scans the <=256 block sums (inclusive)
// ---------------------------------------------------------------------------
__global__ void __launch_bounds__(SCAN_BLK) k_bscan(int NB, int N) {
    __shared__ int s[SCAN_BLK];
    int t = threadIdx.x;
    s[t] = (t < NB) ? g_bsum[t] : 0;
    __syncthreads();
    #pragma unroll
    for (int off = 1; off < SCAN_BLK; off <<= 1) {
        int v = (t >= off) ? s[t - off] : 0;
        __syncthreads();
        s[t] += v;
        __syncthreads();
    }
    if (t < NB) g_boff[t] = s[t];
    if (t == NB - 1) g_ptr[N] = s[t];
}

// ---------------------------------------------------------------------------
// Pass C: per-block exclusive scan + writeout of ptr / self-loop seed / cursor
// ---------------------------------------------------------------------------
__global__ void __launch_bounds__(SCAN_BLK) k_pscan(int N) {
    __shared__ int s[SCAN_BLK];
    int b = blockIdx.x, t = threadIdx.x;
    int base = b * SCAN_TILE + t * SCAN_ITEMS;

    int c[SCAN_ITEMS];
    int sum = 0;
    #pragma unroll
    for (int j = 0; j < SCAN_ITEMS; j++) {
        int i = base + j;
        c[j] = (i < N) ? g_cnt[i] : 0;
        sum += c[j];
    }
    s[t] = sum;
    __syncthreads();
    #pragma unroll
    for (int off = 1; off < SCAN_BLK; off <<= 1) {
        int v = (t >= off) ? s[t - off] : 0;
        __syncthreads();
        s[t] += v;
        __syncthreads();
    }

    int run = (b > 0 ? g_boff[b - 1] : 0) + s[t] - sum;  // exclusive prefix
    #pragma unroll
    for (int j = 0; j < SCAN_ITEMS; j++) {
        int i = base + j;
        if (i < N) {
            g_ptr[i] = run;
            g_csr[run] = i;       // self loop occupies the first slot
            g_cur[i] = run + 1;
            run += c[j];
        }
    }
}

// ---------------------------------------------------------------------------
// CSR build step 3: scatter edge sources by destination
// ---------------------------------------------------------------------------
__global__ void k_scatter(const void* __restrict__ ei, int E) {
    int e = blockIdx.x * blockDim.x + threadIdx.x;
    if (e >= E) return;
    int is32 = g_ei32;
    int row = loadIdx(ei, e, is32);
    int col = loadIdx(ei, (long long)E + e, is32);
    int pos = atomicAdd(&g_cur[row], 1);
    g_csr[pos] = col;
}

// ---------------------------------------------------------------------------
// ID branch: V[id_index[r]] += x[id_index[r]] @ Wid  (fp16 atomics: dup ids)
// ---------------------------------------------------------------------------
__global__ void __launch_bounds__(256)
k_idv(const float* __restrict__ x,
      const void* __restrict__ idix,
      const float* __restrict__ Wid,
      int NUM) {
    __shared__ float As[64][F];
    __shared__ float Ws[32][F];

    int is32 = g_id32;
    int tx = threadIdx.x, ty = threadIdx.y;
    int tid = ty * 16 + tx;
    int rowBase = blockIdx.x * 64;

    #pragma unroll
    for (int i = tid; i < 64 * 32; i += 256) {
        int r = i >> 5, c = (i & 31) << 2;
        int gr = rowBase + r;
        float4 v = make_float4(0.f, 0.f, 0.f, 0.f);
        if (gr < NUM) {
            int src = loadIdx(idix, gr, is32);
            v = *(const float4*)(x + (size_t)src * F + c);
        }
        *(float4*)&As[r][c] = v;
    }

    float acc[4][8];
    #pragma unroll
    for (int i = 0; i < 4; i++)
        #pragma unroll
        for (int j = 0; j < 8; j++) acc[i][j] = 0.0f;

    for (int kb = 0; kb < 4; kb++) {
        __syncthreads();
        #pragma unroll
        for (int i = tid; i < 32 * 32; i += 256) {
            int r = i >> 5, c = (i & 31) << 2;
            *(float4*)&Ws[r][c] = *(const float4*)(Wid + (size_t)(kb * 32 + r) * F + c);
        }
        __syncthreads();
        #pragma unroll
        for (int k = 0; k < 32; k++) {
            float a0 = As[ty * 4 + 0][kb * 32 + k];
            float a1 = As[ty * 4 + 1][kb * 32 + k];
            float a2 = As[ty * 4 + 2][kb * 32 + k];
            float a3 = As[ty * 4 + 3][kb * 32 + k];
            #pragma unroll
            for (int j = 0; j < 8; j++) {
                float w = Ws[k][tx + j * 16];
                acc[0][j] = fmaf(a0, w, acc[0][j]);
                acc[1][j] = fmaf(a1, w, acc[1][j]);
                acc[2][j] = fmaf(a2, w, acc[2][j]);
                acc[3][j] = fmaf(a3, w, acc[3][j]);
            }
        }
    }

    __half* vh = (__half*)g_Vh;
    #pragma unroll
    for (int i = 0; i < 4; i++) {
        int gr = rowBase + ty * 4 + i;
        if (gr >= NUM) continue;
        int dst = loadIdx(idix, gr, is32);
        #pragma unroll
        for (int j = 0; j < 8; j++) {
            int c = tx + j * 16;
            atomicAdd(&vh[(size_t)dst * F + c], __float2half(acc[i][j]));
        }
    }
}

// ---------------------------------------------------------------------------
// CSR aggregation: one warp per destination node. No atomics. fp16 K/V halves
// the gather traffic (256 B/warp per row for each of K and V).
// Softmax shift-invariance: att = relu-dot/4 is bounded ~O(5), no max needed.
// K/V gathers software-pipelined one iteration ahead to hide L2 latency.
// ---------------------------------------------------------------------------
__global__ void __launch_bounds__(256)
k_aggr(float* __restrict__ out, const float* __restrict__ bias, int N) {
    int w = (blockIdx.x * blockDim.x + threadIdx.x) >> 5;
    int lane = threadIdx.x & 31;
    if (w >= N) return;

    int beg = g_ptr[w];
    int end = g_ptr[w + 1];

    float4 q = *(const float4*)&g_Q[(size_t)w * F + lane * 4];
    float4 acc = make_float4(0.f, 0.f, 0.f, 0.f);
    float den = 0.0f;

    // Prologue: deg >= 1 always (self loop)
    int col = g_csr[beg];
    uint2 ku = *(const uint2*)&g_Kh[(size_t)col * (F / 2) + lane * 2];
    uint2 vu = *(const uint2*)&g_Vh[(size_t)col * (F / 2) + lane * 2];

    for (int j = beg; j < end; j++) {
        // Prefetch next iteration's gathers before consuming current values
        int ncol = (j + 1 < end) ? g_csr[j + 1] : 0;
        uint2 nku = *(const uint2*)&g_Kh[(size_t)ncol * (F / 2) + lane * 2];
        uint2 nvu = *(const uint2*)&g_Vh[(size_t)ncol * (F / 2) + lane * 2];

        float2 k0 = __half22float2(*(__half2*)&ku.x);
        float2 k1 = __half22float2(*(__half2*)&ku.y);
        float p = q.x * k0.x + q.y * k0.y + q.z * k1.x + q.w * k1.y;
        p += __shfl_xor_sync(0xFFFFFFFFu, p, 1);
        p += __shfl_xor_sync(0xFFFFFFFFu, p, 2);
        float wt = __expf(p * 0.25f);           // att = dot16 / sqrt(16)

        float2 v0 = __half22float2(*(__half2*)&vu.x);
        float2 v1 = __half22float2(*(__half2*)&vu.y);
        acc.x = fmaf(wt, v0.x, acc.x);
        acc.y = fmaf(wt, v0.y, acc.y);
        acc.z = fmaf(wt, v1.x, acc.z);
        acc.w = fmaf(wt, v1.y, acc.w);
        den += wt;

        ku = nku; vu = nvu;
    }

    float inv = 1.0f / den;
    int c0 = lane * 4;
    float4 r;
    r.x = acc.x * inv + bias[c0 + 0];
    r.y = acc.y * inv + bias[c0 + 1];
    r.z = acc.z * inv + bias[c0 + 2];
    r.w = acc.w * inv + bias[c0 + 3];
    *(float4*)&out[(size_t)w * F + c0] = r;
}

// ---------------------------------------------------------------------------
extern "C" void kernel_launch(void* const* d_in, const int* in_sizes, int n_in,
                              void* d_out, int out_size) {
    const float* x    = (const float*)d_in[0];
    const void*  ei   = d_in[1];
    const void*  idix = d_in[2];
    const float* Wq   = (const float*)d_in[3];
    const float* bq   = (const float*)d_in[4];
    const float* Wk   = (const float*)d_in[5];
    const float* bk   = (const float*)d_in[6];
    const float* Wv   = (const float*)d_in[7];
    const float* Wid  = (const float*)d_in[8];
    const float* bias = (const float*)d_in[9];
    float* out = (float*)d_out;

    int N   = in_sizes[0] / F;
    int E   = in_sizes[1] / 2;
    int NUM = in_sizes[2];
    int NB  = (N + SCAN_TILE - 1) / SCAN_TILE;   // scan blocks (<=256)

    // Unconditional (no static guards allowed): idempotent, capture-safe.
    cudaFuncSetAttribute(k_gemm, cudaFuncAttributeMaxDynamicSharedMemorySize,
                         GEMM_SMEM_BYTES);

    // Launch order puts k_gemm at index 3 (the launch ncu captures).
    k_detect<<<4, 256>>>((const unsigned*)ei, in_sizes[1],
                         (const unsigned*)idix, in_sizes[2]);
    k_init<<<(N + 255) / 256, 256>>>(N);
    k_hist<<<(E + 255) / 256, 256>>>(ei, E);

    k_gemm<<<dim3((N + 63) / 64, 1, 3), 256, GEMM_SMEM_BYTES>>>(x, Wq, bq, Wk, bk, Wv, N);

    k_bsum<<<NB, SCAN_BLK>>>(N);
    k_bscan<<<1, SCAN_BLK>>>(NB, N);
    k_pscan<<<NB, SCAN_BLK>>>(N);
    k_scatter<<<(E + 255) / 256, 256>>>(ei, E);

    dim3 blk(16, 16);
    k_idv<<<(NUM + 63) / 64, blk>>>(x, idix, Wid, NUM);

    long long aggrThreads = (long long)N * 32;
    k_aggr<<<(int)((aggrThreads + 255) / 256), 256>>>(out, bias, N);
}

// round 17
// speedup vs baseline: 1.2600x; 1.2600x over previous
#include <cuda_runtime.h>
#include <cuda_bf16.h>

// Problem constants (shapes fixed by the dataset)
#define F 128
#define HEADS 8
#define NMAX 50000
#define EMAX 600000
#define SLOTS (EMAX + NMAX)
#define SCAN_BLK 256
#define SCAN_ITEMS 4
#define SCAN_TILE (SCAN_BLK * SCAN_ITEMS)   // 1024 counts per block
#define SCAN_MAXB 256                        // up to 256K nodes

// Scratch (device globals: the sanctioned no-alloc workaround)
__device__ float g_Q[NMAX * F];
__device__ float g_K[NMAX * F];
__device__ float g_V[NMAX * F];
__device__ unsigned g_Wsp[3 * 2 * 4 * 16 * F];  // [z][hi/lo][chunk][pair-row][col] packed bf16 pairs
__device__ int   g_cnt[NMAX];       // per-dest degree (incl. self loop)
__device__ int   g_ptr[NMAX + 1];   // CSR row pointers
__device__ int   g_cur[NMAX];       // scatter cursors
__device__ int   g_csr[SLOTS];      // column (source) indices, dest-sorted
__device__ int   g_bsum[SCAN_MAXB]; // per-block count sums
__device__ int   g_boff[SCAN_MAXB]; // inclusive scan of block sums
__device__ int   g_ei32;            // 1 if edge_index is int32, 0 if int64
__device__ int   g_id32;            // 1 if id_index   is int32, 0 if int64

__device__ __forceinline__ int loadIdx(const void* p, long long i, int is32) {
    if (is32) return ((const int*)p)[i];
    return (int)((const long long*)p)[i];
}

// ---------------------------------------------------------------------------
// bf16 split: a = hi + lo + eps, eps ~ 2^-18 |a|  (both halves exact bf16)
// ---------------------------------------------------------------------------
__device__ __forceinline__ void splitb(float a, unsigned short& hi, unsigned short& lo) {
    __nv_bfloat16 h = __float2bfloat16(a);
    float r = a - __bfloat162float(h);     // exact in fp32
    __nv_bfloat16 l = __float2bfloat16(r);
    hi = __bfloat16_as_ushort(h);
    lo = __bfloat16_as_ushort(l);
}

__device__ __forceinline__ unsigned packu(unsigned short e0, unsigned short e1) {
    return (unsigned)e0 | ((unsigned)e1 << 16);   // e0 = even k (low half)
}

__device__ __forceinline__ void mma_bf16(float c[4], const unsigned a[4], const unsigned b[2]) {
    asm volatile(
        "mma.sync.aligned.m16n8k16.row.col.f32.bf16.bf16.f32 "
        "{%0,%1,%2,%3}, {%4,%5,%6,%7}, {%8,%9}, {%0,%1,%2,%3};"
        : "+f"(c[0]), "+f"(c[1]), "+f"(c[2]), "+f"(c[3])
        : "r"(a[0]), "r"(a[1]), "r"(a[2]), "r"(a[3]),
          "r"(b[0]), "r"(b[1]));
}

// ---------------------------------------------------------------------------
// Dtype detection (launch 0): int64 values < 2^31 have all-zero odd (high)
// u32 words; int32 random indices essentially never do. OR-only writes into
// zero-initialized globals => idempotent across graph replays.
// ---------------------------------------------------------------------------
__global__ void k_detect(const unsigned* __restrict__ ei, int eiElems,
                         const unsigned* __restrict__ idx, int idElems) {
    int t = blockIdx.x * blockDim.x + threadIdx.x;  // 0..1023
    int wi = 2 * t + 1;
    if (wi < eiElems && ei[wi] != 0u) atomicOr(&g_ei32, 1);
    if (wi < idElems && idx[wi] != 0u) atomicOr(&g_id32, 1);
}

// ---------------------------------------------------------------------------
// Init: cnt = 1 (self loop)
// ---------------------------------------------------------------------------
__global__ void k_init(int N) {
    int i = blockIdx.x * blockDim.x + threadIdx.x;
    if (i < N) g_cnt[i] = 1;
}

// ---------------------------------------------------------------------------
// Pre-split W (once, not per CTA): for each z, k-pair p, col n pack
// bf16(W[2p][n]),bf16(W[2p+1][n]) hi and lo into the chunked pair layout
// consumed by k_gemm. 3 * 64 * 128 = 24576 threads, ~2 us.
// ---------------------------------------------------------------------------
__global__ void k_wsplit(const float* __restrict__ Wq,
                         const float* __restrict__ Wk,
                         const float* __restrict__ Wv) {
    int t = blockIdx.x * blockDim.x + threadIdx.x;
    if (t >= 3 * 64 * F) return;
    int z = t / (64 * F);
    int rem = t - z * 64 * F;
    int p = rem / F;            // k-pair index 0..63
    int n = rem - p * F;        // column
    const float* W = (z == 0) ? Wq : (z == 1) ? Wk : Wv;

    float w0 = W[(size_t)(2 * p) * F + n];
    float w1 = W[(size_t)(2 * p + 1) * F + n];
    unsigned short h0, l0, h1, l1;
    splitb(w0, h0, l0);
    splitb(w1, h1, l1);

    int kb = p >> 4, pr = p & 15;
    size_t base = ((size_t)z * 2) * 4 * 16 * F;
    g_Wsp[base + ((size_t)kb * 16 + pr) * F + n] = packu(h0, h1);               // hi
    g_Wsp[base + 4 * 16 * F + ((size_t)kb * 16 + pr) * F + n] = packu(l0, l1);  // lo
}

// ---------------------------------------------------------------------------
// bf16x3 GEMM (launch 3 => ncu-profiled): z=0 Q=relu(xWq+bq), z=1 K=relu(xWk+bk),
// z=2 V=xWv. K-chunked (32). W pre-split in gmem: staging is pure uint4 copies.
// A split in-kernel (unique per tile). m16n8k16, 3-pass bf16 split (~2^-18).
// ---------------------------------------------------------------------------
#define AP 20                    // u32 pair stride for A rows (16 data + 4 pad)
#define WP 136                   // u32 col stride for W pair-rows (128 + 8 pad)
#define KCHUNK 32
#define KPAIRS (KCHUNK / 2)      // 16 pair-rows per chunk
#define GEMM_SMEM_BYTES ((64 * AP * 2 + KPAIRS * WP * 2) * 4)

__global__ void __launch_bounds__(256, 2)
k_gemm(const float* __restrict__ x,
       const float* __restrict__ bq, const float* __restrict__ bk,
       int N) {
    extern __shared__ unsigned smu[];
    unsigned* Ahi = smu;                  // [64][AP]
    unsigned* Alo = Ahi + 64 * AP;
    unsigned* Whi = Alo + 64 * AP;        // [KPAIRS][WP]
    unsigned* Wlo = Whi + KPAIRS * WP;

    int z = blockIdx.z;
    const float* bias = (z == 0) ? bq : (z == 1) ? bk : nullptr;
    float* out        = (z == 0) ? g_Q : (z == 1) ? g_K : g_V;
    const unsigned* WspHi = g_Wsp + ((size_t)z * 2) * 4 * 16 * F;
    const unsigned* WspLo = WspHi + 4 * 16 * F;

    int tid = threadIdx.x;
    int rowBase = blockIdx.x * 64;

    int lane = tid & 31, wid = tid >> 5;
    int g = lane >> 2, t4 = lane & 3;
    int wm = (wid & 1) * 32;
    int wn = (wid >> 1) * 32;

    float c[2][4][4];
    #pragma unroll
    for (int mt = 0; mt < 2; mt++)
        #pragma unroll
        for (int nt = 0; nt < 4; nt++)
            #pragma unroll
            for (int j = 0; j < 4; j++) c[mt][nt][j] = 0.0f;

    for (int kb = 0; kb < F / KCHUNK; kb++) {
        if (kb > 0) __syncthreads();      // protect smem reuse across chunks

        // Stage A chunk: 64 rows x 32 k (512 float4 tasks -> 2 packed u32 each)
        #pragma unroll
        for (int i = tid; i < 64 * 8; i += 256) {
            int r = i >> 3, c4 = (i & 7) << 2;       // k offset in chunk
            int gr = rowBase + r;
            float4 v = make_float4(0.f, 0.f, 0.f, 0.f);
            if (gr < N) v = *(const float4*)(x + (size_t)gr * F + kb * KCHUNK + c4);
            unsigned short hx, lx, hy, ly, hz, lz, hw, lw;
            splitb(v.x, hx, lx); splitb(v.y, hy, ly);
            splitb(v.z, hz, lz); splitb(v.w, hw, lw);
            int pc = c4 >> 1;                        // pair column
            Ahi[r * AP + pc]     = packu(hx, hy);
            Ahi[r * AP + pc + 1] = packu(hz, hw);
            Alo[r * AP + pc]     = packu(lx, ly);
            Alo[r * AP + pc + 1] = packu(lz, lw);
        }
        // Stage W chunk: pure uint4 copies of pre-split packed pairs
        const unsigned* wh = WspHi + (size_t)kb * 16 * F;
        const unsigned* wl = WspLo + (size_t)kb * 16 * F;
        #pragma unroll
        for (int i = tid; i < 16 * 32; i += 256) {
            int pr = i >> 5, c4 = (i & 31) << 2;
            uint4 h = *(const uint4*)&wh[pr * F + c4];
            uint4 l = *(const uint4*)&wl[pr * F + c4];
            *(uint4*)&Whi[pr * WP + c4] = h;
            *(uint4*)&Wlo[pr * WP + c4] = l;
        }
        __syncthreads();

        #pragma unroll
        for (int ks = 0; ks < KCHUNK / 16; ks++) {
            int bp = ks * 8;                         // base pair index
            unsigned ah[2][4], al[2][4];
            #pragma unroll
            for (int mt = 0; mt < 2; mt++) {
                int r0 = wm + mt * 16 + g;
                ah[mt][0] = Ahi[r0 * AP + bp + t4];
                ah[mt][1] = Ahi[(r0 + 8) * AP + bp + t4];
                ah[mt][2] = Ahi[r0 * AP + bp + t4 + 4];
                ah[mt][3] = Ahi[(r0 + 8) * AP + bp + t4 + 4];
                al[mt][0] = Alo[r0 * AP + bp + t4];
                al[mt][1] = Alo[(r0 + 8) * AP + bp + t4];
                al[mt][2] = Alo[r0 * AP + bp + t4 + 4];
                al[mt][3] = Alo[(r0 + 8) * AP + bp + t4 + 4];
            }
            unsigned bh[4][2], bl[4][2];
            #pragma unroll
            for (int nt = 0; nt < 4; nt++) {
                int cn = wn + nt * 8 + g;
                bh[nt][0] = Whi[(bp + t4) * WP + cn];
                bh[nt][1] = Whi[(bp + t4 + 4) * WP + cn];
                bl[nt][0] = Wlo[(bp + t4) * WP + cn];
                bl[nt][1] = Wlo[(bp + t4 + 4) * WP + cn];
            }
            #pragma unroll
            for (int mt = 0; mt < 2; mt++)
                #pragma unroll
                for (int nt = 0; nt < 4; nt++) {
                    mma_bf16(c[mt][nt], ah[mt], bh[nt]);
                    mma_bf16(c[mt][nt], ah[mt], bl[nt]);
                    mma_bf16(c[mt][nt], al[mt], bh[nt]);
                }
        }
    }

    // Writeout (float2 per fragment half)
    #pragma unroll
    for (int mt = 0; mt < 2; mt++) {
        int r0 = rowBase + wm + mt * 16 + g;
        #pragma unroll
        for (int nt = 0; nt < 4; nt++) {
            int cn = wn + nt * 8 + 2 * t4;
            float b0 = bias ? bias[cn] : 0.0f;
            float b1 = bias ? bias[cn + 1] : 0.0f;
            if (r0 < N) {
                float v0 = c[mt][nt][0] + b0;
                float v1 = c[mt][nt][1] + b1;
                if (z < 2) { v0 = fmaxf(v0, 0.0f); v1 = fmaxf(v1, 0.0f); }
                *(float2*)&out[(size_t)r0 * F + cn] = make_float2(v0, v1);
            }
            if (r0 + 8 < N) {
                float v0 = c[mt][nt][2] + b0;
                float v1 = c[mt][nt][3] + b1;
                if (z < 2) { v0 = fmaxf(v0, 0.0f); v1 = fmaxf(v1, 0.0f); }
                *(float2*)&out[(size_t)(r0 + 8) * F + cn] = make_float2(v0, v1);
            }
        }
    }
}

// ---------------------------------------------------------------------------
// CSR build step 1: histogram of destinations
// ---------------------------------------------------------------------------
__global__ void k_hist(const void* __restrict__ ei, int E) {
    int e = blockIdx.x * blockDim.x + threadIdx.x;
    if (e >= E) return;
    int row = loadIdx(ei, e, g_ei32);
    atomicAdd(&g_cnt[row], 1);
}

// ---------------------------------------------------------------------------
// Two-level scan, pass A: per-block sums of SCAN_TILE counts
// ---------------------------------------------------------------------------
__global__ void __launch_bounds__(SCAN_BLK) k_bsum(int N) {
    __shared__ int s[SCAN_BLK];
    int b = blockIdx.x, t = threadIdx.x;
    int base = b * SCAN_TILE + t * SCAN_ITEMS;
    int sum = 0;
    #pragma unroll
    for (int j = 0; j < SCAN_ITEMS; j++) {
        int i = base + j;
        if (i < N) sum += g_cnt[i];
    }
    s[t] = sum;
    __syncthreads();
    #pragma unroll
    for (int off = SCAN_BLK / 2; off > 0; off >>= 1) {
        if (t < off) s[t] += s[t + off];
        __syncthreads();
    }
    if (t == 0) g_bsum[b] = s[0];
}

// ---------------------------------------------------------------------------
// Pass B: single small block scans the <=256 block sums (inclusive)
// ---------------------------------------------------------------------------
__global__ void __launch_bounds__(SCAN_BLK) k_bscan(int NB, int N) {
    __shared__ int s[SCAN_BLK];
    int t = threadIdx.x;
    s[t] = (t < NB) ? g_bsum[t] : 0;
    __syncthreads();
    #pragma unroll
    for (int off = 1; off < SCAN_BLK; off <<= 1) {
        int v = (t >= off) ? s[t - off] : 0;
        __syncthreads();
        s[t] += v;
        __syncthreads();
    }
    if (t < NB) g_boff[t] = s[t];
    if (t == NB - 1) g_ptr[N] = s[t];
}

// ---------------------------------------------------------------------------
// Pass C: per-block exclusive scan + writeout of ptr / self-loop seed / cursor
// ---------------------------------------------------------------------------
__global__ void __launch_bounds__(SCAN_BLK) k_pscan(int N) {
    __shared__ int s[SCAN_BLK];
    int b = blockIdx.x, t = threadIdx.x;
    int base = b * SCAN_TILE + t * SCAN_ITEMS;

    int c[SCAN_ITEMS];
    int sum = 0;
    #pragma unroll
    for (int j = 0; j < SCAN_ITEMS; j++) {
        int i = base + j;
        c[j] = (i < N) ? g_cnt[i] : 0;
        sum += c[j];
    }
    s[t] = sum;
    __syncthreads();
    #pragma unroll
    for (int off = 1; off < SCAN_BLK; off <<= 1) {
        int v = (t >= off) ? s[t - off] : 0;
        __syncthreads();
        s[t] += v;
        __syncthreads();
    }

    int run = (b > 0 ? g_boff[b - 1] : 0) + s[t] - sum;  // exclusive prefix
    #pragma unroll
    for (int j = 0; j < SCAN_ITEMS; j++) {
        int i = base + j;
        if (i < N) {
            g_ptr[i] = run;
            g_csr[run] = i;       // self loop occupies the first slot
            g_cur[i] = run + 1;
            run += c[j];
        }
    }
}

// ---------------------------------------------------------------------------
// CSR build step 3: scatter edge sources by destination
// ---------------------------------------------------------------------------
__global__ void k_scatter(const void* __restrict__ ei, int E) {
    int e = blockIdx.x * blockDim.x + threadIdx.x;
    if (e >= E) return;
    int is32 = g_ei32;
    int row = loadIdx(ei, e, is32);
    int col = loadIdx(ei, (long long)E + e, is32);
    int pos = atomicAdd(&g_cur[row], 1);
    g_csr[pos] = col;
}

// ---------------------------------------------------------------------------
// ID branch: g_V[id_index[r]] += x[id_index[r]] @ Wid  (fp32 atomics: dup ids)
// ---------------------------------------------------------------------------
__global__ void __launch_bounds__(256)
k_idv(const float* __restrict__ x,
      const void* __restrict__ idix,
      const float* __restrict__ Wid,
      int NUM) {
    __shared__ float As[64][F];
    __shared__ float Ws[32][F];

    int is32 = g_id32;
    int tx = threadIdx.x, ty = threadIdx.y;
    int tid = ty * 16 + tx;
    int rowBase = blockIdx.x * 64;

    #pragma unroll
    for (int i = tid; i < 64 * 32; i += 256) {
        int r = i >> 5, c = (i & 31) << 2;
        int gr = rowBase + r;
        float4 v = make_float4(0.f, 0.f, 0.f, 0.f);
        if (gr < NUM) {
            int src = loadIdx(idix, gr, is32);
            v = *(const float4*)(x + (size_t)src * F + c);
        }
        *(float4*)&As[r][c] = v;
    }

    float acc[4][8];
    #pragma unroll
    for (int i = 0; i < 4; i++)
        #pragma unroll
        for (int j = 0; j < 8; j++) acc[i][j] = 0.0f;

    for (int kb = 0; kb < 4; kb++) {
        __syncthreads();
        #pragma unroll
        for (int i = tid; i < 32 * 32; i += 256) {
            int r = i >> 5, c = (i & 31) << 2;
            *(float4*)&Ws[r][c] = *(const float4*)(Wid + (size_t)(kb * 32 + r) * F + c);
        }
        __syncthreads();
        #pragma unroll
        for (int k = 0; k < 32; k++) {
            float a0 = As[ty * 4 + 0][kb * 32 + k];
            float a1 = As[ty * 4 + 1][kb * 32 + k];
            float a2 = As[ty * 4 + 2][kb * 32 + k];
            float a3 = As[ty * 4 + 3][kb * 32 + k];
            #pragma unroll
            for (int j = 0; j < 8; j++) {
                float w = Ws[k][tx + j * 16];
                acc[0][j] = fmaf(a0, w, acc[0][j]);
                acc[1][j] = fmaf(a1, w, acc[1][j]);
                acc[2][j] = fmaf(a2, w, acc[2][j]);
                acc[3][j] = fmaf(a3, w, acc[3][j]);
            }
        }
    }

    #pragma unroll
    for (int i = 0; i < 4; i++) {
        int gr = rowBase + ty * 4 + i;
        if (gr >= NUM) continue;
        int dst = loadIdx(idix, gr, is32);
        #pragma unroll
        for (int j = 0; j < 8; j++) {
            int c = tx + j * 16;
            atomicAdd(&g_V[(size_t)dst * F + c], acc[i][j]);
        }
    }
}

// ---------------------------------------------------------------------------
// CSR aggregation: one warp per destination node. No atomics.
// Softmax shift-invariance: att = relu-dot/4 is bounded ~O(5), no max needed.
// K/V gathers software-pipelined one iteration ahead to hide L2 latency.
// ---------------------------------------------------------------------------
__global__ void __launch_bounds__(256)
k_aggr(float* __restrict__ out, const float* __restrict__ bias, int N) {
    int w = (blockIdx.x * blockDim.x + threadIdx.x) >> 5;
    int lane = threadIdx.x & 31;
    if (w >= N) return;

    int beg = g_ptr[w];
    int end = g_ptr[w + 1];

    float4 q = *(const float4*)&g_Q[(size_t)w * F + lane * 4];
    float4 acc = make_float4(0.f, 0.f, 0.f, 0.f);
    float den = 0.0f;

    // Prologue: deg >= 1 always (self loop)
    int col = g_csr[beg];
    float4 k = *(const float4*)&g_K[(size_t)col * F + lane * 4];
    float4 v = *(const float4*)&g_V[(size_t)col * F + lane * 4];

    for (int j = beg; j < end; j++) {
        // Prefetch next iteration's gathers before consuming current values
        int ncol = (j + 1 < end) ? g_csr[j + 1] : 0;
        float4 nk = *(const float4*)&g_K[(size_t)ncol * F + lane * 4];
        float4 nv = *(const float4*)&g_V[(size_t)ncol * F + lane * 4];

        float p = q.x * k.x + q.y * k.y + q.z * k.z + q.w * k.w;
        p += __shfl_xor_sync(0xFFFFFFFFu, p, 1);
        p += __shfl_xor_sync(0xFFFFFFFFu, p, 2);
        float wt = __expf(p * 0.25f);           // att = dot16 / sqrt(16)

        acc.x = fmaf(wt, v.x, acc.x);
        acc.y = fmaf(wt, v.y, acc.y);
        acc.z = fmaf(wt, v.z, acc.z);
        acc.w = fmaf(wt, v.w, acc.w);
        den += wt;

        k = nk; v = nv;
    }

    float inv = 1.0f / den;
    int c0 = lane * 4;
    float4 r;
    r.x = acc.x * inv + bias[c0 + 0];
    r.y = acc.y * inv + bias[c0 + 1];
    r.z = acc.z * inv + bias[c0 + 2];
    r.w = acc.w * inv + bias[c0 + 3];
    *(float4*)&out[(size_t)w * F + c0] = r;
}

// ---------------------------------------------------------------------------
extern "C" void kernel_launch(void* const* d_in, const int* in_sizes, int n_in,
                              void* d_out, int out_size) {
    const float* x    = (const float*)d_in[0];
    const void*  ei   = d_in[1];
    const void*  idix = d_in[2];
    const float* Wq   = (const float*)d_in[3];
    const float* bq   = (const float*)d_in[4];
    const float* Wk   = (const float*)d_in[5];
    const float* bk   = (const float*)d_in[6];
    const float* Wv   = (const float*)d_in[7];
    const float* Wid  = (const float*)d_in[8];
    const float* bias = (const float*)d_in[9];
    float* out = (float*)d_out;

    int N   = in_sizes[0] / F;
    int E   = in_sizes[1] / 2;
    int NUM = in_sizes[2];
    int NB  = (N + SCAN_TILE - 1) / SCAN_TILE;   // scan blocks (<=256)

    // Unconditional (no static guards allowed): idempotent, capture-safe.
    cudaFuncSetAttribute(k_gemm, cudaFuncAttributeMaxDynamicSharedMemorySize,
                         GEMM_SMEM_BYTES);

    // Launch order keeps k_gemm at index 3 (the launch ncu captures).
    k_detect<<<4, 256>>>((const unsigned*)ei, in_sizes[1],
                         (const unsigned*)idix, in_sizes[2]);
    k_init<<<(N + 255) / 256, 256>>>(N);
    k_wsplit<<<(3 * 64 * F + 255) / 256, 256>>>(Wq, Wk, Wv);

    k_gemm<<<dim3((N + 63) / 64, 1, 3), 256, GEMM_SMEM_BYTES>>>(x, bq, bk, N);

    k_hist<<<(E + 255) / 256, 256>>>(ei, E);
    k_bsum<<<NB, SCAN_BLK>>>(N);
    k_bscan<<<1, SCAN_BLK>>>(NB, N);
    k_pscan<<<NB, SCAN_BLK>>>(N);
    k_scatter<<<(E + 255) / 256, 256>>>(ei, E);

    dim3 blk(16, 16);
    k_idv<<<(NUM + 63) / 64, blk>>>(x, idix, Wid, NUM);

    long long aggrThreads = (long long)N * 32;
    k_aggr<<<(int)((aggrThreads + 255) / 256), 256>>>(out, bias, N);
}